// round 6
// baseline (speedup 1.0000x reference)
#include <cuda_runtime.h>
#include <cuda_bf16.h>
#include <cstdint>

// ---------------------------------------------------------------------------
// GCNEncoder: 2-layer GCN, N=100000, E=3200000, 128 -> 32 -> 16.
//
// R5: k_scat1 was pinned at the LTS throughput cap (~820MB L2 traffic:
// 128B gather + 128B atomic RMW per edge). Replace RED-scatter with CSR
// gather-aggregation, but fixing R3's two failures:
//  * CSR ranks come FREE from the histogram atomics (rank = old count),
//    so the fill pass is non-atomic.
//  * Aggregation stages 32 edge ids then issues 8 independent predicated
//    gathers per step (MLP=8) -> L2-throughput bound, not latency bound.
//  * No accumulator arrays: k_fuse folds into agg1's epilogue, final
//    epilogue folds into agg2 (writes d_out). No acc memsets.
// ---------------------------------------------------------------------------

#define N_NODES 100000
#define N_EDGES 3200000
#define IN_C    128
#define HID     32
#define OUT_C   16

#define GEMM_BLOCKS (N_NODES / 32)    // 3125
#define EDGE_BLOCKS (N_EDGES / 256)   // 12500 (exact)
#define G1_BLOCKS   (N_NODES * HID / 256)  // 12500 (exact)

// Scratch (no cudaMalloc allowed) ------------------------------------------
__device__ int   g_degi[N_NODES];          // in-degree histogram
__device__ int   g_off [N_NODES + 1];      // CSR offsets
__device__ int   g_row [N_EDGES];          // decoded int32 source
__device__ int   g_col [N_EDGES];          // decoded int32 target
__device__ int   g_rank[N_EDGES];          // slot within target's CSR segment
__device__ int   g_csr [N_EDGES];          // CSR: source per slot
__device__ float g_dinv[N_NODES];
__device__ float g_g1  [N_NODES * HID];    // x@W1, then scaled by dinv
__device__ float g_g2  [N_NODES * OUT_C];  // dinv * (relu(agg1) @ W2)
__device__ int   g_is64;

__device__ __forceinline__ int edge_row(const void* ei, int e, int is64) {
    return is64 ? (int)((const long long*)ei)[e] : ((const int*)ei)[e];
}
__device__ __forceinline__ int edge_col(const void* ei, int e, int is64) {
    return is64 ? (int)((const long long*)ei)[(size_t)N_EDGES + e]
                : ((const int*)ei)[(size_t)N_EDGES + e];
}

// K0: dtype detection (int64 view of genuine int32 data falls out of [0,N)
// with overwhelming probability over 2048 samples).
__global__ void k_detect(const void* __restrict__ ei) {
    __shared__ int bad;
    if (threadIdx.x == 0) bad = 0;
    __syncthreads();
    const long long* p = (const long long*)ei;
    for (int i = threadIdx.x; i < 2048; i += blockDim.x) {
        long long v = p[i];
        if (v < 0 || v >= N_NODES) atomicOr(&bad, 1);
    }
    __syncthreads();
    if (threadIdx.x == 0) g_is64 = (bad == 0) ? 1 : 0;
}

// K1 (fused): blocks [0,GEMM_BLOCKS) do register-tiled g1 = x@W1 (FMA-bound);
// blocks [GEMM_BLOCKS,+EDGE_BLOCKS) decode indices and build histogram,
// capturing each edge's CSR rank from the same atomic (memory-bound).
__global__ __launch_bounds__(256) void k_fusedA(const float* __restrict__ x,
                                                const float* __restrict__ W1,
                                                const void*  __restrict__ ei) {
    int tid = threadIdx.x;
    if (blockIdx.x >= GEMM_BLOCKS) {
        int e = (blockIdx.x - GEMM_BLOCKS) * 256 + tid;
        int is64 = g_is64;
        int r = edge_row(ei, e, is64);
        int c = edge_col(ei, e, is64);
        g_row[e]  = r;
        g_col[e]  = c;
        g_rank[e] = atomicAdd(&g_degi[c], 1);   // histogram + free CSR slot
        return;
    }
    __shared__ float sW[IN_C * HID];
    __shared__ float sx[32][IN_C];
#pragma unroll
    for (int i = tid; i < (IN_C * HID) / 4; i += 256)
        ((float4*)sW)[i] = ((const float4*)W1)[i];

    int nb = blockIdx.x * 32;
#pragma unroll
    for (int i = tid; i < 32 * (IN_C / 4); i += 256) {
        int row = i >> 5, c4 = i & 31;
        ((float4*)sx[row])[c4] =
            ((const float4*)(x + (size_t)(nb + row) * IN_C))[c4];
    }
    __syncthreads();

    int warp = tid >> 5, lane = tid & 31;
    int n0 = warp * 4;
    float a0 = 0.f, a1 = 0.f, a2 = 0.f, a3 = 0.f;
#pragma unroll 4
    for (int kk = 0; kk < IN_C; kk += 4) {
        float4 xa = *(const float4*)&sx[n0 + 0][kk];
        float4 xb = *(const float4*)&sx[n0 + 1][kk];
        float4 xc = *(const float4*)&sx[n0 + 2][kk];
        float4 xd = *(const float4*)&sx[n0 + 3][kk];
        float w0 = sW[(kk + 0) * HID + lane];
        float w1 = sW[(kk + 1) * HID + lane];
        float w2 = sW[(kk + 2) * HID + lane];
        float w3 = sW[(kk + 3) * HID + lane];
        a0 = fmaf(xa.x, w0, fmaf(xa.y, w1, fmaf(xa.z, w2, fmaf(xa.w, w3, a0))));
        a1 = fmaf(xb.x, w0, fmaf(xb.y, w1, fmaf(xb.z, w2, fmaf(xb.w, w3, a1))));
        a2 = fmaf(xc.x, w0, fmaf(xc.y, w1, fmaf(xc.z, w2, fmaf(xc.w, w3, a2))));
        a3 = fmaf(xd.x, w0, fmaf(xd.y, w1, fmaf(xd.z, w2, fmaf(xd.w, w3, a3))));
    }
    g_g1[(size_t)(nb + n0 + 0) * HID + lane] = a0;
    g_g1[(size_t)(nb + n0 + 1) * HID + lane] = a1;
    g_g1[(size_t)(nb + n0 + 2) * HID + lane] = a2;
    g_g1[(size_t)(nb + n0 + 3) * HID + lane] = a3;
}

// K2: single-block scan -> CSR offsets + dinv.
__global__ __launch_bounds__(1024) void k_scan() {
    __shared__ int ssum[1024];
    const int CH = (N_NODES + 1023) / 1024;
    int t = threadIdx.x;
    int begin = t * CH;
    int end   = begin + CH; if (end > N_NODES) end = N_NODES;
    if (begin > N_NODES) begin = N_NODES;

    int s = 0;
    for (int i = begin; i < end; i++) s += g_degi[i];
    ssum[t] = s;
    __syncthreads();
    for (int off = 1; off < 1024; off <<= 1) {
        int v = (t >= off) ? ssum[t - off] : 0;
        __syncthreads();
        ssum[t] += v;
        __syncthreads();
    }
    int run = (t == 0) ? 0 : ssum[t - 1];
    for (int i = begin; i < end; i++) {
        int d = g_degi[i];
        g_off[i]  = run;
        g_dinv[i] = (d > 0) ? rsqrtf((float)d) : 0.0f;
        run += d;
    }
    if (t == 1023) g_off[N_NODES] = run;
}

// K3 (fused): blocks [0,EDGE_BLOCKS) non-atomic CSR fill;
// blocks [EDGE_BLOCKS,+G1_BLOCKS) scale g1 by dinv in place.
__global__ __launch_bounds__(256) void k_fusedB() {
    int t = threadIdx.x;
    if (blockIdx.x < EDGE_BLOCKS) {
        int e = blockIdx.x * 256 + t;
        int c = g_col[e];
        g_csr[g_off[c] + g_rank[e]] = g_row[e];
    } else {
        int i = (blockIdx.x - EDGE_BLOCKS) * 256 + t;
        g_g1[i] *= g_dinv[i >> 5];              // HID == 32
    }
}

// K4: layer-1 aggregation + fused layer-2 input transform.
// Warp per node, lane = feature. 32 edge ids staged coalesced, then per
// 8-edge group issue 8 independent predicated gathers (MLP=8).
// Epilogue: h = relu(acc*dinv + b1); g2 = dinv * (h @ W2).
__global__ __launch_bounds__(256) void k_agg1(const float* __restrict__ W2,
                                              const float* __restrict__ b1) {
    __shared__ float sW[HID * OUT_C];
    __shared__ float sb1[HID];
    __shared__ float sh[8][HID];
    for (int i = threadIdx.x; i < HID * OUT_C; i += 256) sW[i] = W2[i];
    for (int i = threadIdx.x; i < HID; i += 256) sb1[i] = b1[i];
    __syncthreads();

    int warp = threadIdx.x >> 5, lane = threadIdx.x & 31;
    int node = blockIdx.x * 8 + warp;           // grid = 12500, exact
    int s = g_off[node], e = g_off[node + 1];

    float acc = 0.f;
    for (int chunk = s; chunk < e; chunk += 32) {
        int n = e - chunk; if (n > 32) n = 32;
        int cid = g_csr[chunk + ((lane < n) ? lane : 0)];
        for (int j0 = 0; j0 < n; j0 += 8) {
            float tv[8];
#pragma unroll
            for (int k = 0; k < 8; k++) {
                int rk = __shfl_sync(0xffffffffu, cid, (j0 + k) & 31);
                float v = 0.f;
                if (j0 + k < n) v = g_g1[(size_t)rk * HID + lane];
                tv[k] = v;
            }
            acc += ((tv[0] + tv[1]) + (tv[2] + tv[3])) +
                   ((tv[4] + tv[5]) + (tv[6] + tv[7]));
        }
    }

    float dv = g_dinv[node];
    float h = fmaxf(fmaf(acc, dv, sb1[lane]), 0.0f);
    sh[warp][lane] = h;
    __syncwarp();
    if (lane < OUT_C) {
        float o = 0.f;
#pragma unroll
        for (int k = 0; k < HID; k++)
            o = fmaf(sh[warp][k], sW[k * OUT_C + lane], o);
        g_g2[(size_t)node * OUT_C + lane] = o * dv;
    }
}

// K5: layer-2 aggregation + epilogue -> d_out.
// Warp per node; half-warps (16 lanes = OUT_C feats) process disjoint 8-edge
// groups, cross-half combine via shfl.
__global__ __launch_bounds__(256) void k_agg2(float* __restrict__ out,
                                              const float* __restrict__ b2) {
    int warp = threadIdx.x >> 5, lane = threadIdx.x & 31;
    int node = blockIdx.x * 8 + warp;           // grid = 12500, exact
    int half = lane >> 4, l = lane & 15;
    int s = g_off[node], e = g_off[node + 1];

    float acc = 0.f;
    for (int chunk = s; chunk < e; chunk += 32) {
        int n = e - chunk; if (n > 32) n = 32;
        int cid = g_csr[chunk + ((lane < n) ? lane : 0)];
#pragma unroll
        for (int j0 = 0; j0 < 32; j0 += 16) {
            if (j0 >= n) break;
            float tv[8];
#pragma unroll
            for (int k = 0; k < 8; k++) {
                int j = j0 + 8 * half + k;
                int rk = __shfl_sync(0xffffffffu, cid, j & 31);
                float v = 0.f;
                if (j < n) v = g_g2[(size_t)rk * OUT_C + l];
                tv[k] = v;
            }
            acc += ((tv[0] + tv[1]) + (tv[2] + tv[3])) +
                   ((tv[4] + tv[5]) + (tv[6] + tv[7]));
        }
    }
    acc += __shfl_down_sync(0xffffffffu, acc, 16);
    if (half == 0)
        out[(size_t)node * OUT_C + l] = acc * g_dinv[node] + b2[l];
}

// K6: zero any tail of d_out beyond N*OUT_C (tuple scalar slot).
__global__ void k_tail(float* __restrict__ out, int out_size) {
    int t = N_NODES * OUT_C + blockIdx.x * blockDim.x + threadIdx.x;
    if (t < out_size) out[t] = 0.0f;
}

// ---------------------------------------------------------------------------
extern "C" void kernel_launch(void* const* d_in, const int* in_sizes, int n_in,
                              void* d_out, int out_size) {
    const float* x  = (const float*)d_in[0];
    const void*  ei = d_in[1];
    const float* W1 = (const float*)d_in[2];
    const float* b1 = (const float*)d_in[3];
    const float* W2 = (const float*)d_in[4];
    const float* b2 = (const float*)d_in[5];
    float* out = (float*)d_out;

    void* p_degi;
    cudaGetSymbolAddress(&p_degi, g_degi);
    cudaMemsetAsync(p_degi, 0, (size_t)N_NODES * sizeof(int));

    k_detect<<<1, 256>>>(ei);
    k_fusedA<<<GEMM_BLOCKS + EDGE_BLOCKS, 256>>>(x, W1, ei);
    k_scan  <<<1, 1024>>>();
    k_fusedB<<<EDGE_BLOCKS + G1_BLOCKS, 256>>>();
    k_agg1  <<<N_NODES / 8, 256>>>(W2, b1);
    k_agg2  <<<N_NODES / 8, 256>>>(out, b2);

    int tail = out_size - N_NODES * OUT_C;
    if (tail > 0)
        k_tail<<<(tail + 255) / 256, 256>>>(out, out_size);
}

// round 7
// speedup vs baseline: 1.4225x; 1.4225x over previous
#include <cuda_runtime.h>
#include <cuda_fp16.h>
#include <cstdint>

// ---------------------------------------------------------------------------
// GCNEncoder: 2-layer GCN, N=100000, E=3200000, 128 -> 32 -> 16.
//
// R6 = R4 (best: 234us, RED-scatter design) + scatter-byte reduction:
//  * g1/g2 feature tables stored fp16 (gather bytes halved); accumulation
//    stays fp32 via red.global.add.v4.f32 (error ~3e-4 << 1e-3).
//  * dinv source-scaling folded into scat1 (broadcast dinv[r]); the g1
//    rescale pass is gone, GEMM writes fp16 directly.
//  * scat1: 4 threads/edge (LDG.128 fp16 + 2x red.v4); scat2: 2 threads/edge.
// CSR/gather designs (R3, R5) both lost: warp-per-node gathers are L2-latency
// bound; fire-and-forget REDs run at LTS throughput. Do not revisit.
// ---------------------------------------------------------------------------

#define N_NODES 100000
#define N_EDGES 3200000
#define IN_C    128
#define HID     32
#define OUT_C   16

#define GEMM_BLOCKS (N_NODES / 32)    // 3125
#define EDGE_BLOCKS (N_EDGES / 256)   // 12500 (exact)

// Scratch (no cudaMalloc allowed) ------------------------------------------
__device__ int    g_degi[N_NODES];
__device__ int    g_row [N_EDGES];
__device__ int    g_col [N_EDGES];
__device__ float  g_dinv[N_NODES];
__device__ __half g_g1h[N_NODES * HID];    // x@W1 (UNscaled), fp16
__device__ float  g_acc1[N_NODES * HID];   // layer-1 scatter accumulator
__device__ __half g_g2h[N_NODES * OUT_C];  // dinv*(relu(...)@W2), fp16
__device__ float  g_acc2[N_NODES * OUT_C]; // layer-2 scatter accumulator
__device__ int    g_is64;

__device__ __forceinline__ int edge_row(const void* ei, int e, int is64) {
    return is64 ? (int)((const long long*)ei)[e] : ((const int*)ei)[e];
}
__device__ __forceinline__ int edge_col(const void* ei, int e, int is64) {
    return is64 ? (int)((const long long*)ei)[(size_t)N_EDGES + e]
                : ((const int*)ei)[(size_t)N_EDGES + e];
}

// K0: dtype detection (int64 view of genuine int32 data leaves [0,N) with
// overwhelming probability across 2048 samples).
__global__ void k_detect(const void* __restrict__ ei) {
    __shared__ int bad;
    if (threadIdx.x == 0) bad = 0;
    __syncthreads();
    const long long* p = (const long long*)ei;
    for (int i = threadIdx.x; i < 2048; i += blockDim.x) {
        long long v = p[i];
        if (v < 0 || v >= N_NODES) atomicOr(&bad, 1);
    }
    __syncthreads();
    if (threadIdx.x == 0) g_is64 = (bad == 0) ? 1 : 0;
}

// K1 (fused): blocks [0,GEMM_BLOCKS) register-tiled g1h = fp16(x@W1);
// blocks [GEMM_BLOCKS,+EDGE_BLOCKS) decode indices + degree histogram.
__global__ __launch_bounds__(256) void k_fusedA(const float* __restrict__ x,
                                                const float* __restrict__ W1,
                                                const void*  __restrict__ ei) {
    int tid = threadIdx.x;
    if (blockIdx.x >= GEMM_BLOCKS) {
        int e = (blockIdx.x - GEMM_BLOCKS) * 256 + tid;
        int is64 = g_is64;
        int r = edge_row(ei, e, is64);
        int c = edge_col(ei, e, is64);
        g_row[e] = r;
        g_col[e] = c;
        atomicAdd(&g_degi[c], 1);
        return;
    }
    __shared__ float sW[IN_C * HID];
    __shared__ float sx[32][IN_C];
#pragma unroll
    for (int i = tid; i < (IN_C * HID) / 4; i += 256)
        ((float4*)sW)[i] = ((const float4*)W1)[i];

    int nb = blockIdx.x * 32;
#pragma unroll
    for (int i = tid; i < 32 * (IN_C / 4); i += 256) {
        int row = i >> 5, c4 = i & 31;
        ((float4*)sx[row])[c4] =
            ((const float4*)(x + (size_t)(nb + row) * IN_C))[c4];
    }
    __syncthreads();

    int warp = tid >> 5, lane = tid & 31;
    int n0 = warp * 4;
    float a0 = 0.f, a1 = 0.f, a2 = 0.f, a3 = 0.f;
#pragma unroll 4
    for (int kk = 0; kk < IN_C; kk += 4) {
        float4 xa = *(const float4*)&sx[n0 + 0][kk];
        float4 xb = *(const float4*)&sx[n0 + 1][kk];
        float4 xc = *(const float4*)&sx[n0 + 2][kk];
        float4 xd = *(const float4*)&sx[n0 + 3][kk];
        float w0 = sW[(kk + 0) * HID + lane];
        float w1 = sW[(kk + 1) * HID + lane];
        float w2 = sW[(kk + 2) * HID + lane];
        float w3 = sW[(kk + 3) * HID + lane];
        a0 = fmaf(xa.x, w0, fmaf(xa.y, w1, fmaf(xa.z, w2, fmaf(xa.w, w3, a0))));
        a1 = fmaf(xb.x, w0, fmaf(xb.y, w1, fmaf(xb.z, w2, fmaf(xb.w, w3, a1))));
        a2 = fmaf(xc.x, w0, fmaf(xc.y, w1, fmaf(xc.z, w2, fmaf(xc.w, w3, a2))));
        a3 = fmaf(xd.x, w0, fmaf(xd.y, w1, fmaf(xd.z, w2, fmaf(xd.w, w3, a3))));
    }
    g_g1h[(size_t)(nb + n0 + 0) * HID + lane] = __float2half(a0);
    g_g1h[(size_t)(nb + n0 + 1) * HID + lane] = __float2half(a1);
    g_g1h[(size_t)(nb + n0 + 2) * HID + lane] = __float2half(a2);
    g_g1h[(size_t)(nb + n0 + 3) * HID + lane] = __float2half(a3);
}

// K2: dinv = rsqrt(deg) or 0.
__global__ void k_dinv() {
    int t = blockIdx.x * blockDim.x + threadIdx.x;
    if (t >= N_NODES) return;
    int d = g_degi[t];
    g_dinv[t] = (d > 0) ? rsqrtf((float)d) : 0.0f;
}

// K3: layer-1 scatter. 4 threads/edge. Each thread: LDG.128 (8 fp16),
// scale by dinv[r], two red.v4.f32 into the fp32 accumulator.
__global__ __launch_bounds__(256) void k_scat1() {
    int t = blockIdx.x * 256 + threadIdx.x;      // grid exact: E*4
    int e = t >> 2, q = t & 3;
    int r = g_row[e];
    int c = g_col[e];
    float dv = g_dinv[r];
    const uint4 p = *(const uint4*)((const __half2*)g_g1h + (size_t)r * 16 + q * 4);
    float2 f0 = __half22float2(*(const __half2*)&p.x);
    float2 f1 = __half22float2(*(const __half2*)&p.y);
    float2 f2 = __half22float2(*(const __half2*)&p.z);
    float2 f3 = __half22float2(*(const __half2*)&p.w);
    float* dst = g_acc1 + (size_t)c * HID + q * 8;
    asm volatile("red.global.add.v4.f32 [%0], {%1,%2,%3,%4};"
                 :: "l"(dst), "f"(f0.x * dv), "f"(f0.y * dv),
                    "f"(f1.x * dv), "f"(f1.y * dv) : "memory");
    asm volatile("red.global.add.v4.f32 [%0], {%1,%2,%3,%4};"
                 :: "l"(dst + 4), "f"(f2.x * dv), "f"(f2.y * dv),
                    "f"(f3.x * dv), "f"(f3.y * dv) : "memory");
}

// K4: h = relu(acc1*dinv + b1); g2h = fp16(dinv * (h @ W2)). Warp per node.
__global__ __launch_bounds__(256) void k_fuse(const float* __restrict__ W2,
                                              const float* __restrict__ b1) {
    __shared__ float sW[HID * OUT_C];
    __shared__ float sb1[HID];
    __shared__ float sh[8][HID];
    for (int i = threadIdx.x; i < HID * OUT_C; i += 256) sW[i] = W2[i];
    for (int i = threadIdx.x; i < HID; i += 256) sb1[i] = b1[i];
    __syncthreads();

    int warp = threadIdx.x >> 5, lane = threadIdx.x & 31;
    int node = blockIdx.x * 8 + warp;
    if (node >= N_NODES) return;

    float dv = g_dinv[node];
    float h = fmaxf(fmaf(g_acc1[(size_t)node * HID + lane], dv, sb1[lane]), 0.0f);
    sh[warp][lane] = h;
    __syncwarp();

    if (lane < OUT_C) {
        float acc = 0.0f;
#pragma unroll
        for (int k = 0; k < HID; k++)
            acc = fmaf(sh[warp][k], sW[k * OUT_C + lane], acc);
        g_g2h[(size_t)node * OUT_C + lane] = __float2half(acc * dv);
    }
}

// K5: layer-2 scatter. 2 threads/edge, LDG.128 fp16 + 2x red.v4.
__global__ __launch_bounds__(256) void k_scat2() {
    int t = blockIdx.x * 256 + threadIdx.x;      // grid exact: E*2
    int e = t >> 1, q = t & 1;
    int r = g_row[e];
    int c = g_col[e];
    const uint4 p = *(const uint4*)((const __half2*)g_g2h + (size_t)r * 8 + q * 4);
    float2 f0 = __half22float2(*(const __half2*)&p.x);
    float2 f1 = __half22float2(*(const __half2*)&p.y);
    float2 f2 = __half22float2(*(const __half2*)&p.z);
    float2 f3 = __half22float2(*(const __half2*)&p.w);
    float* dst = g_acc2 + (size_t)c * OUT_C + q * 8;
    asm volatile("red.global.add.v4.f32 [%0], {%1,%2,%3,%4};"
                 :: "l"(dst), "f"(f0.x), "f"(f0.y), "f"(f1.x), "f"(f1.y) : "memory");
    asm volatile("red.global.add.v4.f32 [%0], {%1,%2,%3,%4};"
                 :: "l"(dst + 4), "f"(f2.x), "f"(f2.y), "f"(f3.x), "f"(f3.y) : "memory");
}

// K6: out = acc2*dinv + b2; zero-fill tail (tuple scalar slot).
__global__ void k_final(float* __restrict__ out, const float* __restrict__ b2,
                        int out_size) {
    int t = blockIdx.x * blockDim.x + threadIdx.x;
    if (t >= out_size) return;
    if (t < N_NODES * OUT_C) {
        int c = t >> 4, j = t & 15;              // OUT_C == 16
        out[t] = g_acc2[t] * g_dinv[c] + b2[j];
    } else {
        out[t] = 0.0f;
    }
}

// ---------------------------------------------------------------------------
extern "C" void kernel_launch(void* const* d_in, const int* in_sizes, int n_in,
                              void* d_out, int out_size) {
    const float* x  = (const float*)d_in[0];
    const void*  ei = d_in[1];
    const float* W1 = (const float*)d_in[2];
    const float* b1 = (const float*)d_in[3];
    const float* W2 = (const float*)d_in[4];
    const float* b2 = (const float*)d_in[5];
    float* out = (float*)d_out;

    void *p_degi, *p_acc1, *p_acc2;
    cudaGetSymbolAddress(&p_degi, g_degi);
    cudaGetSymbolAddress(&p_acc1, g_acc1);
    cudaGetSymbolAddress(&p_acc2, g_acc2);
    cudaMemsetAsync(p_degi, 0, (size_t)N_NODES * sizeof(int));
    cudaMemsetAsync(p_acc1, 0, (size_t)N_NODES * HID * sizeof(float));
    cudaMemsetAsync(p_acc2, 0, (size_t)N_NODES * OUT_C * sizeof(float));

    k_detect<<<1, 256>>>(ei);
    k_fusedA<<<GEMM_BLOCKS + EDGE_BLOCKS, 256>>>(x, W1, ei);
    k_dinv  <<<(N_NODES + 255) / 256, 256>>>();
    k_scat1 <<<(N_EDGES * 4) / 256, 256>>>();
    k_fuse  <<<(N_NODES + 7) / 8, 256>>>(W2, b1);
    k_scat2 <<<(N_EDGES * 2) / 256, 256>>>();
    k_final <<<(out_size + 255) / 256, 256>>>(out, b2, out_size);
}